// round 12
// baseline (speedup 1.0000x reference)
#include <cuda_runtime.h>
#include <cuda_fp16.h>
#include <cstdint>
#include <math.h>

// ---------------------------------------------------------------------------
// QuantDeepseekMLP on sm_103a (legacy mma.sync; tcgen05 PTX rejected by the
// harness's compute_103 virtual arch).
// R11: fp16-accumulate HMMA (2x rate) within each K=64 tile, folded into an
// fp32 master accumulator once per tile (bounded 4-rounding chunks keep
// rel_err ~5-7e-4 < 1e-3). Both GEMMs 128 thr / 2 CTAs/SM (R10 win).
// ---------------------------------------------------------------------------

#define Mdim 4096
#define Hdim 5120
#define Idim 12288

__device__ __half g_x16[(size_t)Mdim * Hdim];
__device__ __half g_wg16[(size_t)Idim * Hdim];
__device__ __half g_wu16[(size_t)Idim * Hdim];
__device__ __half g_wd16[(size_t)Hdim * Idim];
__device__ __half g_h[(size_t)Mdim * Idim];
__device__ int g_wflag;   // 0=int8, 1=int32, 2=float32 weight storage

// ------------------------- dtype detection --------------------------------
__global__ void detect_w_kernel(const int* __restrict__ w) {
    if (threadIdx.x == 0 && blockIdx.x == 0) {
        int all_i32 = 1, all_f32 = 1;
        for (int i = 0; i < 256; i++) {
            int v = w[i];
            if (v < -127 || v > 127) all_i32 = 0;
            float f = __int_as_float(v);
            if (!(isfinite(f) && fabsf(f) <= 127.0f && f == rintf(f)))
                all_f32 = 0;
        }
        g_wflag = all_i32 ? 1 : (all_f32 ? 2 : 0);
    }
}

// ------------------------------ converters --------------------------------
__global__ void cvt_f32_f16_kernel(const float* __restrict__ in,
                                   __half* __restrict__ out, int n) {
    int i = (blockIdx.x * blockDim.x + threadIdx.x) * 4;
    if (i < n) {
        float4 v = *(const float4*)(in + i);
        *(__half2*)(out + i)     = __floats2half2_rn(v.x, v.y);
        *(__half2*)(out + i + 2) = __floats2half2_rn(v.z, v.w);
    }
}

__device__ __forceinline__ void cvt_w8(const void* in, __half* out, int i) {
    const int flag = g_wflag;
    float v[8];
    if (flag == 1) {
        const int4* p = (const int4*)((const int*)in + i);
        int4 a = p[0], b = p[1];
        v[0]=(float)a.x; v[1]=(float)a.y; v[2]=(float)a.z; v[3]=(float)a.w;
        v[4]=(float)b.x; v[5]=(float)b.y; v[6]=(float)b.z; v[7]=(float)b.w;
    } else if (flag == 2) {
        const float4* p = (const float4*)((const float*)in + i);
        float4 a = p[0], b = p[1];
        v[0]=a.x; v[1]=a.y; v[2]=a.z; v[3]=a.w;
        v[4]=b.x; v[5]=b.y; v[6]=b.z; v[7]=b.w;
    } else {
        uint2 raw = *(const uint2*)((const int8_t*)in + i);
        const int8_t* b = (const int8_t*)&raw;
        #pragma unroll
        for (int j = 0; j < 8; j++) v[j] = (float)b[j];
    }
    #pragma unroll
    for (int j = 0; j < 8; j += 2)
        *(__half2*)(out + i + j) = __floats2half2_rn(v[j], v[j + 1]);
}

__global__ void cvt_w_all_kernel(const void* w0, const void* w1, const void* w2,
                                 __half* o0, __half* o1, __half* o2, int n) {
    int i = (blockIdx.x * blockDim.x + threadIdx.x) * 8;
    if (i >= n) return;
    const void* src = (blockIdx.y == 0) ? w0 : (blockIdx.y == 1) ? w1 : w2;
    __half* dst = (blockIdx.y == 0) ? o0 : (blockIdx.y == 1) ? o1 : o2;
    cvt_w8(src, dst, i);
}

// --------------------------- PTX helpers -----------------------------------
__device__ __forceinline__ uint32_t smem_u32(const void* p) {
    return (uint32_t)__cvta_generic_to_shared(p);
}
__device__ __forceinline__ void cp_async16(uint32_t smem, const void* gmem) {
    asm volatile("cp.async.cg.shared.global [%0], [%1], 16;\n" :: "r"(smem), "l"(gmem));
}
__device__ __forceinline__ void cp_commit() {
    asm volatile("cp.async.commit_group;\n" ::: "memory");
}
template <int N>
__device__ __forceinline__ void cp_wait() {
    asm volatile("cp.async.wait_group %0;\n" :: "n"(N) : "memory");
}
__device__ __forceinline__ void ldsm_x4(uint32_t* r, uint32_t addr) {
    asm volatile("ldmatrix.sync.aligned.m8n8.x4.shared.b16 {%0,%1,%2,%3}, [%4];"
                 : "=r"(r[0]), "=r"(r[1]), "=r"(r[2]), "=r"(r[3]) : "r"(addr));
}
// fp16-accumulate MMA (2x tensor rate vs f32 acc)
__device__ __forceinline__ void mma16816_f16_zero(uint32_t* c, const uint32_t* a,
                                                  const uint32_t* b) {
    asm volatile(
        "mma.sync.aligned.m16n8k16.row.col.f16.f16.f16.f16 "
        "{%0,%1}, {%2,%3,%4,%5}, {%6,%7}, {%8,%8};\n"
        : "=r"(c[0]), "=r"(c[1])
        : "r"(a[0]), "r"(a[1]), "r"(a[2]), "r"(a[3]),
          "r"(b[0]), "r"(b[1]), "r"(0u));
}
__device__ __forceinline__ void mma16816_f16_acc(uint32_t* c, const uint32_t* a,
                                                 const uint32_t* b) {
    asm volatile(
        "mma.sync.aligned.m16n8k16.row.col.f16.f16.f16.f16 "
        "{%0,%1}, {%2,%3,%4,%5}, {%6,%7}, {%0,%1};\n"
        : "+r"(c[0]), "+r"(c[1])
        : "r"(a[0]), "r"(a[1]), "r"(a[2]), "r"(a[3]),
          "r"(b[0]), "r"(b[1]));
}
// fold fp16 chunk accumulator into fp32 master
__device__ __forceinline__ void fold_h2(float* acc, const uint32_t* c16) {
    float2 lo = __half22float2(*(const __half2*)&c16[0]);
    float2 hi = __half22float2(*(const __half2*)&c16[1]);
    acc[0] += lo.x; acc[1] += lo.y; acc[2] += hi.x; acc[3] += hi.y;
}

#define SWZ(o) ((o) ^ (((o) >> 3) & 0x70))

// =========== fused gate+up GEMM: 128x64 h-tile, 128 thr, 2 CTAs/SM =========
#define GU_STAGES 3
#define GU_A_BYTES (128 * 128)
#define GU_STAGE_BYTES (GU_A_BYTES + 128 * 128)    // 32 KB
#define GU_SMEM (GU_STAGES * GU_STAGE_BYTES + 1024)

__global__ __launch_bounds__(128, 2)
void gemm_gateup(const __half* __restrict__ A, const __half* __restrict__ Bg_w,
                 const __half* __restrict__ Bu_w,
                 const float* __restrict__ sg, const float* __restrict__ su,
                 __half* __restrict__ outp, int N, int K) {
    extern __shared__ char smem_raw[];
    const uint32_t sbase = (smem_u32(smem_raw) + 1023) & ~1023u;

    const int tid  = threadIdx.x;
    const int lane = tid & 31;
    const int warp = tid >> 5;
    const int wm = (warp >> 1) * 64;
    const int wn = (warp & 1) * 64;           // virtual B-row offset
    const int m0 = blockIdx.x * 128;          // m fastest (L2 locality)
    const int n0 = blockIdx.y * 64;           // h column tile (64 wide)
    const int KT = K >> 6;

    const int g  = lane >> 3;
    const int li = lane & 7;

    const size_t pitch = (size_t)K * 2;
    const char* Ag = (const char*)A + (size_t)m0 * pitch;
    const char* Gg = (const char*)Bg_w + (size_t)n0 * pitch;
    const char* Ug = (const char*)Bu_w + (size_t)n0 * pitch;

    float acc[4][8][4];
    #pragma unroll
    for (int a = 0; a < 4; a++)
        #pragma unroll
        for (int b = 0; b < 8; b++)
            #pragma unroll
            for (int c = 0; c < 4; c++) acc[a][b][c] = 0.f;

    auto load_stage = [&](int slot, int kt) {
        const size_t k0b = (size_t)kt * 128;
        const uint32_t ab = sbase + slot * GU_STAGE_BYTES;
        const uint32_t bb = ab + GU_A_BYTES;
        #pragma unroll
        for (int i = 0; i < 16; i++) {
            int idx = i * 128 + tid;           // 0..2047
            if (idx < 1024) {                  // A: 128 rows
                int r = idx >> 3, cb = (idx & 7) * 16;
                cp_async16(ab + SWZ(r * 128 + cb), Ag + (size_t)r * pitch + k0b + cb);
            } else {                           // B: 128 virtual rows
                int j = idx - 1024;            // 0..1023
                int r = j >> 3, cb = (j & 7) * 16;
                int blk = r >> 5, within = r & 31;
                int w32 = (blk >> 1) * 32 + within;
                const char* src = (blk & 1) ? Ug : Gg;
                cp_async16(bb + SWZ(r * 128 + cb), src + (size_t)w32 * pitch + k0b + cb);
            }
        }
        cp_commit();
    };

    load_stage(0, 0);
    if (KT > 1) load_stage(1, 1);

    uint32_t arow[4], brow[4];
    #pragma unroll
    for (int mi = 0; mi < 4; mi++)
        arow[mi] = (uint32_t)(wm + mi * 16 + ((g & 1) ? 8 : 0) + li) * 128;
    #pragma unroll
    for (int bi = 0; bi < 4; bi++)
        brow[bi] = (uint32_t)(wn + bi * 16 + ((g >> 1) ? 8 : 0) + li) * 128;
    const uint32_t acol = (g >> 1) ? 16u : 0u;
    const uint32_t bcol = (g & 1) ? 16u : 0u;

    for (int kt = 0; kt < KT; kt++) {
        const int rem = KT - 1 - kt;
        if (rem >= 1) cp_wait<1>(); else cp_wait<0>();
        __syncthreads();
        if (kt + 2 < KT) load_stage((kt + 2) % GU_STAGES, kt + 2);

        const uint32_t ab = sbase + (kt % GU_STAGES) * GU_STAGE_BYTES;
        const uint32_t bb = ab + GU_A_BYTES;

        uint32_t c16[4][8][2];                 // fp16 chunk accumulators
        #pragma unroll
        for (int ks = 0; ks < 4; ks++) {
            const uint32_t kb = ks * 32;
            uint32_t af[4][4], bf[4][4];
            #pragma unroll
            for (int mi = 0; mi < 4; mi++)
                ldsm_x4(af[mi], ab + SWZ(arow[mi] + kb + acol));
            #pragma unroll
            for (int bi = 0; bi < 4; bi++)
                ldsm_x4(bf[bi], bb + SWZ(brow[bi] + kb + bcol));
            #pragma unroll
            for (int mi = 0; mi < 4; mi++)
                #pragma unroll
                for (int nj = 0; nj < 8; nj++) {
                    if (ks == 0)
                        mma16816_f16_zero(c16[mi][nj], af[mi], &bf[nj >> 1][(nj & 1) * 2]);
                    else
                        mma16816_f16_acc(c16[mi][nj], af[mi], &bf[nj >> 1][(nj & 1) * 2]);
                }
        }
        #pragma unroll
        for (int mi = 0; mi < 4; mi++)
            #pragma unroll
            for (int nj = 0; nj < 8; nj++)
                fold_h2(acc[mi][nj], c16[mi][nj]);
    }

    // epilogue: h = silu(gate*sg/127) * (up*su/127), fp16
    const float inv = 1.0f / 127.0f;
    const int cbase = n0 + (wn >> 1);
    #pragma unroll
    for (int mi = 0; mi < 4; mi++) {
        int r = m0 + wm + mi * 16 + (lane >> 2);
        #pragma unroll
        for (int nj = 0; nj < 4; nj++) {
            int col = cbase + nj * 8 + (lane & 3) * 2;
            float sg0 = sg[col] * inv, sg1 = sg[col + 1] * inv;
            float su0 = su[col] * inv, su1 = su[col + 1] * inv;
            float g00 = acc[mi][nj][0] * sg0, g01 = acc[mi][nj][1] * sg1;
            float g10 = acc[mi][nj][2] * sg0, g11 = acc[mi][nj][3] * sg1;
            float u00 = acc[mi][nj + 4][0] * su0, u01 = acc[mi][nj + 4][1] * su1;
            float u10 = acc[mi][nj + 4][2] * su0, u11 = acc[mi][nj + 4][3] * su1;
            float h00 = u00 * g00 / (1.0f + __expf(-g00));
            float h01 = u01 * g01 / (1.0f + __expf(-g01));
            float h10 = u10 * g10 / (1.0f + __expf(-g10));
            float h11 = u11 * g11 / (1.0f + __expf(-g11));
            *(__half2*)(outp + (size_t)r * N + col)       = __floats2half2_rn(h00, h01);
            *(__half2*)(outp + (size_t)(r + 8) * N + col) = __floats2half2_rn(h10, h11);
        }
    }
}

// ============ down GEMM: 128x128 tile, 128 threads, 2 CTAs/SM ===============
#define DN_STAGES 3
#define DN_A_BYTES (128 * 128)
#define DN_STAGE_BYTES (2 * DN_A_BYTES)            // 32 KB
#define DN_SMEM (DN_STAGES * DN_STAGE_BYTES + 1024)

__global__ __launch_bounds__(128, 2)
void gemm_down(const __half* __restrict__ A, const __half* __restrict__ Bw,
               const float* __restrict__ scale,
               float* __restrict__ outp, int N, int K) {
    extern __shared__ char smem_raw[];
    const uint32_t sbase = (smem_u32(smem_raw) + 1023) & ~1023u;

    const int tid  = threadIdx.x;
    const int lane = tid & 31;
    const int warp = tid >> 5;
    const int wm = (warp >> 1) * 64;          // 0 or 64
    const int wn = (warp & 1) * 64;           // 0 or 64
    const int m0 = blockIdx.x * 128;          // m fastest
    const int n0 = blockIdx.y * 128;
    const int KT = K >> 6;

    const int g  = lane >> 3;
    const int li = lane & 7;

    const size_t pitch = (size_t)K * 2;
    const char* Ag = (const char*)A + (size_t)m0 * pitch;
    const char* Bg = (const char*)Bw + (size_t)n0 * pitch;

    float acc[4][8][4];
    #pragma unroll
    for (int a = 0; a < 4; a++)
        #pragma unroll
        for (int b = 0; b < 8; b++)
            #pragma unroll
            for (int c = 0; c < 4; c++) acc[a][b][c] = 0.f;

    auto load_stage = [&](int slot, int kt) {
        const size_t k0b = (size_t)kt * 128;
        const uint32_t ab = sbase + slot * DN_STAGE_BYTES;
        const uint32_t bb = ab + DN_A_BYTES;
        #pragma unroll
        for (int i = 0; i < 16; i++) {
            int idx = i * 128 + tid;          // 0..2047
            if (idx < 1024) {
                int r = idx >> 3, cb = (idx & 7) * 16;
                cp_async16(ab + SWZ(r * 128 + cb), Ag + (size_t)r * pitch + k0b + cb);
            } else {
                int j = idx - 1024;
                int r = j >> 3, cb = (j & 7) * 16;
                cp_async16(bb + SWZ(r * 128 + cb), Bg + (size_t)r * pitch + k0b + cb);
            }
        }
        cp_commit();
    };

    load_stage(0, 0);
    if (KT > 1) load_stage(1, 1);

    uint32_t arow[4], brow[4];
    #pragma unroll
    for (int mi = 0; mi < 4; mi++)
        arow[mi] = (uint32_t)(wm + mi * 16 + ((g & 1) ? 8 : 0) + li) * 128;
    #pragma unroll
    for (int bi = 0; bi < 4; bi++)
        brow[bi] = (uint32_t)(wn + bi * 16 + ((g >> 1) ? 8 : 0) + li) * 128;
    const uint32_t acol = (g >> 1) ? 16u : 0u;
    const uint32_t bcol = (g & 1) ? 16u : 0u;

    for (int kt = 0; kt < KT; kt++) {
        const int rem = KT - 1 - kt;
        if (rem >= 1) cp_wait<1>(); else cp_wait<0>();
        __syncthreads();
        if (kt + 2 < KT) load_stage((kt + 2) % DN_STAGES, kt + 2);

        const uint32_t ab = sbase + (kt % DN_STAGES) * DN_STAGE_BYTES;
        const uint32_t bb = ab + DN_A_BYTES;

        uint32_t c16[4][8][2];
        #pragma unroll
        for (int ks = 0; ks < 4; ks++) {
            const uint32_t kb = ks * 32;
            uint32_t af[4][4], bf[4][4];
            #pragma unroll
            for (int mi = 0; mi < 4; mi++)
                ldsm_x4(af[mi], ab + SWZ(arow[mi] + kb + acol));
            #pragma unroll
            for (int bi = 0; bi < 4; bi++)
                ldsm_x4(bf[bi], bb + SWZ(brow[bi] + kb + bcol));
            #pragma unroll
            for (int mi = 0; mi < 4; mi++)
                #pragma unroll
                for (int nj = 0; nj < 8; nj++) {
                    if (ks == 0)
                        mma16816_f16_zero(c16[mi][nj], af[mi], &bf[nj >> 1][(nj & 1) * 2]);
                    else
                        mma16816_f16_acc(c16[mi][nj], af[mi], &bf[nj >> 1][(nj & 1) * 2]);
                }
        }
        #pragma unroll
        for (int mi = 0; mi < 4; mi++)
            #pragma unroll
            for (int nj = 0; nj < 8; nj++)
                fold_h2(acc[mi][nj], c16[mi][nj]);
    }

    const float inv = 1.0f / 127.0f;
    #pragma unroll
    for (int mi = 0; mi < 4; mi++) {
        int r = m0 + wm + mi * 16 + (lane >> 2);
        #pragma unroll
        for (int nj = 0; nj < 8; nj++) {
            int col = n0 + wn + nj * 8 + (lane & 3) * 2;
            float s0 = scale[col] * inv;
            float s1 = scale[col + 1] * inv;
            *(float2*)(outp + (size_t)r * N + col) =
                make_float2(acc[mi][nj][0] * s0, acc[mi][nj][1] * s1);
            *(float2*)(outp + (size_t)(r + 8) * N + col) =
                make_float2(acc[mi][nj][2] * s0, acc[mi][nj][3] * s1);
        }
    }
}

// ------------------------------ launcher -----------------------------------
extern "C" void kernel_launch(void* const* d_in, const int* in_sizes, int n_in,
                              void* d_out, int out_size) {
    const float* x  = (const float*)d_in[0];
    const void*  wg = d_in[1];
    const float* sg = (const float*)d_in[2];
    const void*  wu = d_in[3];
    const float* su = (const float*)d_in[4];
    const void*  wd = d_in[5];
    const float* sd = (const float*)d_in[6];

    const int H = in_sizes[6];            // 5120
    const int I = in_sizes[2];            // 12288
    const int M = in_sizes[0] / H;        // 4096

    __half *px16, *pwg, *pwu, *pwd, *ph;
    cudaGetSymbolAddress((void**)&px16, g_x16);
    cudaGetSymbolAddress((void**)&pwg,  g_wg16);
    cudaGetSymbolAddress((void**)&pwu,  g_wu16);
    cudaGetSymbolAddress((void**)&pwd,  g_wd16);
    cudaGetSymbolAddress((void**)&ph,   g_h);

    cudaFuncSetAttribute(gemm_gateup, cudaFuncAttributeMaxDynamicSharedMemorySize, GU_SMEM);
    cudaFuncSetAttribute(gemm_down,   cudaFuncAttributeMaxDynamicSharedMemorySize, DN_SMEM);

    detect_w_kernel<<<1, 32>>>((const int*)wg);

    {
        int n = M * H;
        cvt_f32_f16_kernel<<<(n / 4 + 255) / 256, 256>>>(x, px16, n);
        int nw = I * H;
        dim3 gw((nw / 8 + 255) / 256, 3);
        cvt_w_all_kernel<<<gw, 256>>>(wg, wu, wd, pwg, pwu, pwd, nw);
    }

    // Fused gate+up: h = silu(x@Wg^T*sg/127) * (x@Wu^T*su/127)   [M, I] fp16
    dim3 g1(M / 128, I / 64);    // (32, 192) — 2 CTAs/SM
    gemm_gateup<<<g1, 128, GU_SMEM>>>(px16, pwg, pwu, sg, su, ph, I, H);

    // Down: out = (h @ Wd^T) * sd/127    [M, H] fp32
    dim3 g3(M / 128, H / 128);   // (32, 40) — 2 CTAs/SM
    gemm_down<<<g3, 128, DN_SMEM>>>(ph, pwd, sd, (float*)d_out, H, I);
}

// round 13
// speedup vs baseline: 1.1994x; 1.1994x over previous
#include <cuda_runtime.h>
#include <cuda_fp16.h>
#include <cstdint>
#include <math.h>

// ---------------------------------------------------------------------------
// QuantDeepseekMLP on sm_103a (legacy mma.sync; tcgen05 PTX rejected by the
// harness's compute_103 virtual arch).
// R13: f32-acc HMMA (R11 showed f16-acc is NOT faster here). Occupancy push:
// 32x64 warp tiles, 256 thr/CTA, 2 CTAs/SM => 4 warps/SMSP to hide
// barrier/drain bubbles (the lever that actually moved tensor% in R10).
// ---------------------------------------------------------------------------

#define Mdim 4096
#define Hdim 5120
#define Idim 12288

__device__ __half g_x16[(size_t)Mdim * Hdim];
__device__ __half g_wg16[(size_t)Idim * Hdim];
__device__ __half g_wu16[(size_t)Idim * Hdim];
__device__ __half g_wd16[(size_t)Hdim * Idim];
__device__ __half g_h[(size_t)Mdim * Idim];
__device__ int g_wflag;   // 0=int8, 1=int32, 2=float32 weight storage

// ------------------------- dtype detection --------------------------------
__global__ void detect_w_kernel(const int* __restrict__ w) {
    if (threadIdx.x == 0 && blockIdx.x == 0) {
        int all_i32 = 1, all_f32 = 1;
        for (int i = 0; i < 256; i++) {
            int v = w[i];
            if (v < -127 || v > 127) all_i32 = 0;
            float f = __int_as_float(v);
            if (!(isfinite(f) && fabsf(f) <= 127.0f && f == rintf(f)))
                all_f32 = 0;
        }
        g_wflag = all_i32 ? 1 : (all_f32 ? 2 : 0);
    }
}

// ------------------------------ converters --------------------------------
__global__ void cvt_f32_f16_kernel(const float* __restrict__ in,
                                   __half* __restrict__ out, int n) {
    int i = (blockIdx.x * blockDim.x + threadIdx.x) * 4;
    if (i < n) {
        float4 v = *(const float4*)(in + i);
        *(__half2*)(out + i)     = __floats2half2_rn(v.x, v.y);
        *(__half2*)(out + i + 2) = __floats2half2_rn(v.z, v.w);
    }
}

__device__ __forceinline__ void cvt_w8(const void* in, __half* out, int i) {
    const int flag = g_wflag;
    float v[8];
    if (flag == 1) {
        const int4* p = (const int4*)((const int*)in + i);
        int4 a = p[0], b = p[1];
        v[0]=(float)a.x; v[1]=(float)a.y; v[2]=(float)a.z; v[3]=(float)a.w;
        v[4]=(float)b.x; v[5]=(float)b.y; v[6]=(float)b.z; v[7]=(float)b.w;
    } else if (flag == 2) {
        const float4* p = (const float4*)((const float*)in + i);
        float4 a = p[0], b = p[1];
        v[0]=a.x; v[1]=a.y; v[2]=a.z; v[3]=a.w;
        v[4]=b.x; v[5]=b.y; v[6]=b.z; v[7]=b.w;
    } else {
        uint2 raw = *(const uint2*)((const int8_t*)in + i);
        const int8_t* b = (const int8_t*)&raw;
        #pragma unroll
        for (int j = 0; j < 8; j++) v[j] = (float)b[j];
    }
    #pragma unroll
    for (int j = 0; j < 8; j += 2)
        *(__half2*)(out + i + j) = __floats2half2_rn(v[j], v[j + 1]);
}

__global__ void cvt_w_all_kernel(const void* w0, const void* w1, const void* w2,
                                 __half* o0, __half* o1, __half* o2, int n) {
    int i = (blockIdx.x * blockDim.x + threadIdx.x) * 8;
    if (i >= n) return;
    const void* src = (blockIdx.y == 0) ? w0 : (blockIdx.y == 1) ? w1 : w2;
    __half* dst = (blockIdx.y == 0) ? o0 : (blockIdx.y == 1) ? o1 : o2;
    cvt_w8(src, dst, i);
}

// --------------------------- PTX helpers -----------------------------------
__device__ __forceinline__ uint32_t smem_u32(const void* p) {
    return (uint32_t)__cvta_generic_to_shared(p);
}
__device__ __forceinline__ void cp_async16(uint32_t smem, const void* gmem) {
    asm volatile("cp.async.cg.shared.global [%0], [%1], 16;\n" :: "r"(smem), "l"(gmem));
}
__device__ __forceinline__ void cp_commit() {
    asm volatile("cp.async.commit_group;\n" ::: "memory");
}
template <int N>
__device__ __forceinline__ void cp_wait() {
    asm volatile("cp.async.wait_group %0;\n" :: "n"(N) : "memory");
}
__device__ __forceinline__ void ldsm_x4(uint32_t* r, uint32_t addr) {
    asm volatile("ldmatrix.sync.aligned.m8n8.x4.shared.b16 {%0,%1,%2,%3}, [%4];"
                 : "=r"(r[0]), "=r"(r[1]), "=r"(r[2]), "=r"(r[3]) : "r"(addr));
}
__device__ __forceinline__ void mma16816(float* d, const uint32_t* a,
                                         const uint32_t* b) {
    asm volatile(
        "mma.sync.aligned.m16n8k16.row.col.f32.f16.f16.f32 "
        "{%0,%1,%2,%3}, {%4,%5,%6,%7}, {%8,%9}, {%0,%1,%2,%3};\n"
        : "+f"(d[0]), "+f"(d[1]), "+f"(d[2]), "+f"(d[3])
        : "r"(a[0]), "r"(a[1]), "r"(a[2]), "r"(a[3]), "r"(b[0]), "r"(b[1]));
}

#define SWZ(o) ((o) ^ (((o) >> 3) & 0x70))

// =========== fused gate+up GEMM: 128x64 h-tile, 256 thr, 2 CTAs/SM =========
// Warp grid 4(M) x 2(N-virtual): wm = (warp&3)*32, wn = (warp>>2)*64.
// B smem 128 virtual rows: [g(c0..31)|u(c0..31)|g(c32..63)|u(c32..63)].
// acc[2][8][4]: nj<4 = gate, nj>=4 = up for h cols [n0+(wn>>1), +32).
#define GU_STAGES 3
#define GU_A_BYTES (128 * 128)
#define GU_STAGE_BYTES (GU_A_BYTES + 128 * 128)    // 32 KB
#define GU_SMEM (GU_STAGES * GU_STAGE_BYTES + 1024)

__global__ __launch_bounds__(256, 2)
void gemm_gateup(const __half* __restrict__ A, const __half* __restrict__ Bg_w,
                 const __half* __restrict__ Bu_w,
                 const float* __restrict__ sg, const float* __restrict__ su,
                 __half* __restrict__ outp, int N, int K) {
    extern __shared__ char smem_raw[];
    const uint32_t sbase = (smem_u32(smem_raw) + 1023) & ~1023u;

    const int tid  = threadIdx.x;
    const int lane = tid & 31;
    const int warp = tid >> 5;
    const int wm = (warp & 3) * 32;           // M offset (4 warps)
    const int wn = (warp >> 2) * 64;          // virtual B-row offset (2 warps)
    const int m0 = blockIdx.x * 128;          // m fastest (L2 locality)
    const int n0 = blockIdx.y * 64;           // h column tile (64 wide)
    const int KT = K >> 6;

    const int g  = lane >> 3;
    const int li = lane & 7;

    const size_t pitch = (size_t)K * 2;
    const char* Ag = (const char*)A + (size_t)m0 * pitch;
    const char* Gg = (const char*)Bg_w + (size_t)n0 * pitch;
    const char* Ug = (const char*)Bu_w + (size_t)n0 * pitch;

    float acc[2][8][4];
    #pragma unroll
    for (int a = 0; a < 2; a++)
        #pragma unroll
        for (int b = 0; b < 8; b++)
            #pragma unroll
            for (int c = 0; c < 4; c++) acc[a][b][c] = 0.f;

    auto load_stage = [&](int slot, int kt) {
        const size_t k0b = (size_t)kt * 128;
        const uint32_t ab = sbase + slot * GU_STAGE_BYTES;
        const uint32_t bb = ab + GU_A_BYTES;
        #pragma unroll
        for (int i = 0; i < 8; i++) {
            int idx = i * 256 + tid;           // 0..2047
            if (idx < 1024) {                  // A: 128 rows
                int r = idx >> 3, cb = (idx & 7) * 16;
                cp_async16(ab + SWZ(r * 128 + cb), Ag + (size_t)r * pitch + k0b + cb);
            } else {                           // B: 128 virtual rows
                int j = idx - 1024;            // 0..1023
                int r = j >> 3, cb = (j & 7) * 16;
                int blk = r >> 5, within = r & 31;
                int w32 = (blk >> 1) * 32 + within;
                const char* src = (blk & 1) ? Ug : Gg;
                cp_async16(bb + SWZ(r * 128 + cb), src + (size_t)w32 * pitch + k0b + cb);
            }
        }
        cp_commit();
    };

    load_stage(0, 0);
    if (KT > 1) load_stage(1, 1);

    uint32_t arow[2], brow[4];
    #pragma unroll
    for (int mi = 0; mi < 2; mi++)
        arow[mi] = (uint32_t)(wm + mi * 16 + ((g & 1) ? 8 : 0) + li) * 128;
    #pragma unroll
    for (int bi = 0; bi < 4; bi++)
        brow[bi] = (uint32_t)(wn + bi * 16 + ((g >> 1) ? 8 : 0) + li) * 128;
    const uint32_t acol = (g >> 1) ? 16u : 0u;
    const uint32_t bcol = (g & 1) ? 16u : 0u;

    for (int kt = 0; kt < KT; kt++) {
        const int rem = KT - 1 - kt;
        if (rem >= 1) cp_wait<1>(); else cp_wait<0>();
        __syncthreads();
        if (kt + 2 < KT) load_stage((kt + 2) % GU_STAGES, kt + 2);

        const uint32_t ab = sbase + (kt % GU_STAGES) * GU_STAGE_BYTES;
        const uint32_t bb = ab + GU_A_BYTES;

        #pragma unroll
        for (int ks = 0; ks < 4; ks++) {
            const uint32_t kb = ks * 32;
            uint32_t af[2][4], bf[4][4];
            #pragma unroll
            for (int mi = 0; mi < 2; mi++)
                ldsm_x4(af[mi], ab + SWZ(arow[mi] + kb + acol));
            #pragma unroll
            for (int bi = 0; bi < 4; bi++)
                ldsm_x4(bf[bi], bb + SWZ(brow[bi] + kb + bcol));
            #pragma unroll
            for (int mi = 0; mi < 2; mi++)
                #pragma unroll
                for (int nj = 0; nj < 8; nj++)
                    mma16816(acc[mi][nj], af[mi], &bf[nj >> 1][(nj & 1) * 2]);
        }
    }

    // epilogue: h = silu(gate*sg/127) * (up*su/127), fp16
    const float inv = 1.0f / 127.0f;
    const int cbase = n0 + (wn >> 1);
    #pragma unroll
    for (int mi = 0; mi < 2; mi++) {
        int r = m0 + wm + mi * 16 + (lane >> 2);
        #pragma unroll
        for (int nj = 0; nj < 4; nj++) {
            int col = cbase + nj * 8 + (lane & 3) * 2;
            float sg0 = sg[col] * inv, sg1 = sg[col + 1] * inv;
            float su0 = su[col] * inv, su1 = su[col + 1] * inv;
            float g00 = acc[mi][nj][0] * sg0, g01 = acc[mi][nj][1] * sg1;
            float g10 = acc[mi][nj][2] * sg0, g11 = acc[mi][nj][3] * sg1;
            float u00 = acc[mi][nj + 4][0] * su0, u01 = acc[mi][nj + 4][1] * su1;
            float u10 = acc[mi][nj + 4][2] * su0, u11 = acc[mi][nj + 4][3] * su1;
            float h00 = u00 * g00 / (1.0f + __expf(-g00));
            float h01 = u01 * g01 / (1.0f + __expf(-g01));
            float h10 = u10 * g10 / (1.0f + __expf(-g10));
            float h11 = u11 * g11 / (1.0f + __expf(-g11));
            *(__half2*)(outp + (size_t)r * N + col)       = __floats2half2_rn(h00, h01);
            *(__half2*)(outp + (size_t)(r + 8) * N + col) = __floats2half2_rn(h10, h11);
        }
    }
}

// ========= down GEMM: 128x128 tile, 256 thr (4x2 warps), 2 CTAs/SM =========
#define DN_STAGES 3
#define DN_A_BYTES (128 * 128)
#define DN_STAGE_BYTES (2 * DN_A_BYTES)            // 32 KB
#define DN_SMEM (DN_STAGES * DN_STAGE_BYTES + 1024)

__global__ __launch_bounds__(256, 2)
void gemm_down(const __half* __restrict__ A, const __half* __restrict__ Bw,
               const float* __restrict__ scale,
               float* __restrict__ outp, int N, int K) {
    extern __shared__ char smem_raw[];
    const uint32_t sbase = (smem_u32(smem_raw) + 1023) & ~1023u;

    const int tid  = threadIdx.x;
    const int lane = tid & 31;
    const int warp = tid >> 5;
    const int wm = (warp & 3) * 32;           // M offset
    const int wn = (warp >> 2) * 64;          // N offset
    const int m0 = blockIdx.x * 128;          // m fastest
    const int n0 = blockIdx.y * 128;
    const int KT = K >> 6;

    const int g  = lane >> 3;
    const int li = lane & 7;

    const size_t pitch = (size_t)K * 2;
    const char* Ag = (const char*)A + (size_t)m0 * pitch;
    const char* Bg = (const char*)Bw + (size_t)n0 * pitch;

    float acc[2][8][4];
    #pragma unroll
    for (int a = 0; a < 2; a++)
        #pragma unroll
        for (int b = 0; b < 8; b++)
            #pragma unroll
            for (int c = 0; c < 4; c++) acc[a][b][c] = 0.f;

    auto load_stage = [&](int slot, int kt) {
        const size_t k0b = (size_t)kt * 128;
        const uint32_t ab = sbase + slot * DN_STAGE_BYTES;
        const uint32_t bb = ab + DN_A_BYTES;
        #pragma unroll
        for (int i = 0; i < 8; i++) {
            int idx = i * 256 + tid;          // 0..2047
            if (idx < 1024) {
                int r = idx >> 3, cb = (idx & 7) * 16;
                cp_async16(ab + SWZ(r * 128 + cb), Ag + (size_t)r * pitch + k0b + cb);
            } else {
                int j = idx - 1024;
                int r = j >> 3, cb = (j & 7) * 16;
                cp_async16(bb + SWZ(r * 128 + cb), Bg + (size_t)r * pitch + k0b + cb);
            }
        }
        cp_commit();
    };

    load_stage(0, 0);
    if (KT > 1) load_stage(1, 1);

    uint32_t arow[2], brow[4];
    #pragma unroll
    for (int mi = 0; mi < 2; mi++)
        arow[mi] = (uint32_t)(wm + mi * 16 + ((g & 1) ? 8 : 0) + li) * 128;
    #pragma unroll
    for (int bi = 0; bi < 4; bi++)
        brow[bi] = (uint32_t)(wn + bi * 16 + ((g >> 1) ? 8 : 0) + li) * 128;
    const uint32_t acol = (g >> 1) ? 16u : 0u;
    const uint32_t bcol = (g & 1) ? 16u : 0u;

    for (int kt = 0; kt < KT; kt++) {
        const int rem = KT - 1 - kt;
        if (rem >= 1) cp_wait<1>(); else cp_wait<0>();
        __syncthreads();
        if (kt + 2 < KT) load_stage((kt + 2) % DN_STAGES, kt + 2);

        const uint32_t ab = sbase + (kt % DN_STAGES) * DN_STAGE_BYTES;
        const uint32_t bb = ab + DN_A_BYTES;

        #pragma unroll
        for (int ks = 0; ks < 4; ks++) {
            const uint32_t kb = ks * 32;
            uint32_t af[2][4], bf[4][4];
            #pragma unroll
            for (int mi = 0; mi < 2; mi++)
                ldsm_x4(af[mi], ab + SWZ(arow[mi] + kb + acol));
            #pragma unroll
            for (int bi = 0; bi < 4; bi++)
                ldsm_x4(bf[bi], bb + SWZ(brow[bi] + kb + bcol));
            #pragma unroll
            for (int mi = 0; mi < 2; mi++)
                #pragma unroll
                for (int nj = 0; nj < 8; nj++)
                    mma16816(acc[mi][nj], af[mi], &bf[nj >> 1][(nj & 1) * 2]);
        }
    }

    const float inv = 1.0f / 127.0f;
    #pragma unroll
    for (int mi = 0; mi < 2; mi++) {
        int r = m0 + wm + mi * 16 + (lane >> 2);
        #pragma unroll
        for (int nj = 0; nj < 8; nj++) {
            int col = n0 + wn + nj * 8 + (lane & 3) * 2;
            float s0 = scale[col] * inv;
            float s1 = scale[col + 1] * inv;
            *(float2*)(outp + (size_t)r * N + col) =
                make_float2(acc[mi][nj][0] * s0, acc[mi][nj][1] * s1);
            *(float2*)(outp + (size_t)(r + 8) * N + col) =
                make_float2(acc[mi][nj][2] * s0, acc[mi][nj][3] * s1);
        }
    }
}

// ------------------------------ launcher -----------------------------------
extern "C" void kernel_launch(void* const* d_in, const int* in_sizes, int n_in,
                              void* d_out, int out_size) {
    const float* x  = (const float*)d_in[0];
    const void*  wg = d_in[1];
    const float* sg = (const float*)d_in[2];
    const void*  wu = d_in[3];
    const float* su = (const float*)d_in[4];
    const void*  wd = d_in[5];
    const float* sd = (const float*)d_in[6];

    const int H = in_sizes[6];            // 5120
    const int I = in_sizes[2];            // 12288
    const int M = in_sizes[0] / H;        // 4096

    __half *px16, *pwg, *pwu, *pwd, *ph;
    cudaGetSymbolAddress((void**)&px16, g_x16);
    cudaGetSymbolAddress((void**)&pwg,  g_wg16);
    cudaGetSymbolAddress((void**)&pwu,  g_wu16);
    cudaGetSymbolAddress((void**)&pwd,  g_wd16);
    cudaGetSymbolAddress((void**)&ph,   g_h);

    cudaFuncSetAttribute(gemm_gateup, cudaFuncAttributeMaxDynamicSharedMemorySize, GU_SMEM);
    cudaFuncSetAttribute(gemm_down,   cudaFuncAttributeMaxDynamicSharedMemorySize, DN_SMEM);

    detect_w_kernel<<<1, 32>>>((const int*)wg);

    {
        int n = M * H;
        cvt_f32_f16_kernel<<<(n / 4 + 255) / 256, 256>>>(x, px16, n);
        int nw = I * H;
        dim3 gw((nw / 8 + 255) / 256, 3);
        cvt_w_all_kernel<<<gw, 256>>>(wg, wu, wd, pwg, pwu, pwd, nw);
    }

    // Fused gate+up: h = silu(x@Wg^T*sg/127) * (x@Wu^T*su/127)   [M, I] fp16
    dim3 g1(M / 128, I / 64);    // (32, 192) — 2 CTAs/SM, 16 warps/SM
    gemm_gateup<<<g1, 256, GU_SMEM>>>(px16, pwg, pwu, sg, su, ph, I, H);

    // Down: out = (h @ Wd^T) * sd/127    [M, H] fp32
    dim3 g3(M / 128, H / 128);   // (32, 40) — 2 CTAs/SM
    gemm_down<<<g3, 256, DN_SMEM>>>(ph, pwd, sd, (float*)d_out, H, I);
}

// round 15
// speedup vs baseline: 1.3673x; 1.1400x over previous
#include <cuda_runtime.h>
#include <cuda_fp16.h>
#include <cstdint>
#include <math.h>
#include <type_traits>

// ---------------------------------------------------------------------------
// QuantDeepseekMLP on sm_103a (legacy mma.sync; tcgen05 PTX rejected by the
// harness's compute_103 virtual arch).
// R14: exact R10 config (64x64 warp tiles, 128 thr, 2 CTAs/SM — the measured
// sweet spot) + mainloop unrolled by STAGES with compile-time slot indices
// (kills the %3 modulo + runtime smem-base math that showed as 22% alu).
// ---------------------------------------------------------------------------

#define Mdim 4096
#define Hdim 5120
#define Idim 12288

__device__ __half g_x16[(size_t)Mdim * Hdim];
__device__ __half g_wg16[(size_t)Idim * Hdim];
__device__ __half g_wu16[(size_t)Idim * Hdim];
__device__ __half g_wd16[(size_t)Hdim * Idim];
__device__ __half g_h[(size_t)Mdim * Idim];
__device__ int g_wflag;   // 0=int8, 1=int32, 2=float32 weight storage

// ------------------------- dtype detection --------------------------------
__global__ void detect_w_kernel(const int* __restrict__ w) {
    if (threadIdx.x == 0 && blockIdx.x == 0) {
        int all_i32 = 1, all_f32 = 1;
        for (int i = 0; i < 256; i++) {
            int v = w[i];
            if (v < -127 || v > 127) all_i32 = 0;
            float f = __int_as_float(v);
            if (!(isfinite(f) && fabsf(f) <= 127.0f && f == rintf(f)))
                all_f32 = 0;
        }
        g_wflag = all_i32 ? 1 : (all_f32 ? 2 : 0);
    }
}

// ------------------------------ converters --------------------------------
__global__ void cvt_f32_f16_kernel(const float* __restrict__ in,
                                   __half* __restrict__ out, int n) {
    int i = (blockIdx.x * blockDim.x + threadIdx.x) * 4;
    if (i < n) {
        float4 v = *(const float4*)(in + i);
        *(__half2*)(out + i)     = __floats2half2_rn(v.x, v.y);
        *(__half2*)(out + i + 2) = __floats2half2_rn(v.z, v.w);
    }
}

__device__ __forceinline__ void cvt_w8(const void* in, __half* out, int i) {
    const int flag = g_wflag;
    float v[8];
    if (flag == 1) {
        const int4* p = (const int4*)((const int*)in + i);
        int4 a = p[0], b = p[1];
        v[0]=(float)a.x; v[1]=(float)a.y; v[2]=(float)a.z; v[3]=(float)a.w;
        v[4]=(float)b.x; v[5]=(float)b.y; v[6]=(float)b.z; v[7]=(float)b.w;
    } else if (flag == 2) {
        const float4* p = (const float4*)((const float*)in + i);
        float4 a = p[0], b = p[1];
        v[0]=a.x; v[1]=a.y; v[2]=a.z; v[3]=a.w;
        v[4]=b.x; v[5]=b.y; v[6]=b.z; v[7]=b.w;
    } else {
        uint2 raw = *(const uint2*)((const int8_t*)in + i);
        const int8_t* b = (const int8_t*)&raw;
        #pragma unroll
        for (int j = 0; j < 8; j++) v[j] = (float)b[j];
    }
    #pragma unroll
    for (int j = 0; j < 8; j += 2)
        *(__half2*)(out + i + j) = __floats2half2_rn(v[j], v[j + 1]);
}

__global__ void cvt_w_all_kernel(const void* w0, const void* w1, const void* w2,
                                 __half* o0, __half* o1, __half* o2, int n) {
    int i = (blockIdx.x * blockDim.x + threadIdx.x) * 8;
    if (i >= n) return;
    const void* src = (blockIdx.y == 0) ? w0 : (blockIdx.y == 1) ? w1 : w2;
    __half* dst = (blockIdx.y == 0) ? o0 : (blockIdx.y == 1) ? o1 : o2;
    cvt_w8(src, dst, i);
}

// --------------------------- PTX helpers -----------------------------------
__device__ __forceinline__ uint32_t smem_u32(const void* p) {
    return (uint32_t)__cvta_generic_to_shared(p);
}
__device__ __forceinline__ void cp_async16(uint32_t smem, const void* gmem) {
    asm volatile("cp.async.cg.shared.global [%0], [%1], 16;\n" :: "r"(smem), "l"(gmem));
}
__device__ __forceinline__ void cp_commit() {
    asm volatile("cp.async.commit_group;\n" ::: "memory");
}
template <int N>
__device__ __forceinline__ void cp_wait() {
    asm volatile("cp.async.wait_group %0;\n" :: "n"(N) : "memory");
}
__device__ __forceinline__ void ldsm_x4(uint32_t* r, uint32_t addr) {
    asm volatile("ldmatrix.sync.aligned.m8n8.x4.shared.b16 {%0,%1,%2,%3}, [%4];"
                 : "=r"(r[0]), "=r"(r[1]), "=r"(r[2]), "=r"(r[3]) : "r"(addr));
}
__device__ __forceinline__ void mma16816(float* d, const uint32_t* a,
                                         const uint32_t* b) {
    asm volatile(
        "mma.sync.aligned.m16n8k16.row.col.f32.f16.f16.f32 "
        "{%0,%1,%2,%3}, {%4,%5,%6,%7}, {%8,%9}, {%0,%1,%2,%3};\n"
        : "+f"(d[0]), "+f"(d[1]), "+f"(d[2]), "+f"(d[3])
        : "r"(a[0]), "r"(a[1]), "r"(a[2]), "r"(a[3]), "r"(b[0]), "r"(b[1]));
}

#define SWZ(o) ((o) ^ (((o) >> 3) & 0x70))

// =========== fused gate+up GEMM: 128x64 h-tile, 128 thr, 2 CTAs/SM =========
#define GU_STAGES 3
#define GU_A_BYTES (128 * 128)
#define GU_STAGE_BYTES (GU_A_BYTES + 128 * 128)    // 32 KB
#define GU_SMEM (GU_STAGES * GU_STAGE_BYTES + 1024)

__global__ __launch_bounds__(128, 2)
void gemm_gateup(const __half* __restrict__ A, const __half* __restrict__ Bg_w,
                 const __half* __restrict__ Bu_w,
                 const float* __restrict__ sg, const float* __restrict__ su,
                 __half* __restrict__ outp, int N, int K) {
    extern __shared__ char smem_raw[];
    const uint32_t sbase = (smem_u32(smem_raw) + 1023) & ~1023u;

    const int tid  = threadIdx.x;
    const int lane = tid & 31;
    const int warp = tid >> 5;
    const int wm = (warp >> 1) * 64;
    const int wn = (warp & 1) * 64;           // virtual B-row offset
    const int m0 = blockIdx.x * 128;          // m fastest (L2 locality)
    const int n0 = blockIdx.y * 64;           // h column tile (64 wide)
    const int KT = K >> 6;

    const int g  = lane >> 3;
    const int li = lane & 7;

    const size_t pitch = (size_t)K * 2;
    const char* Ag = (const char*)A + (size_t)m0 * pitch;
    const char* Gg = (const char*)Bg_w + (size_t)n0 * pitch;
    const char* Ug = (const char*)Bu_w + (size_t)n0 * pitch;

    float acc[4][8][4];
    #pragma unroll
    for (int a = 0; a < 4; a++)
        #pragma unroll
        for (int b = 0; b < 8; b++)
            #pragma unroll
            for (int c = 0; c < 4; c++) acc[a][b][c] = 0.f;

    auto load_stage = [&](int slot, int kt) {
        const size_t k0b = (size_t)kt * 128;
        const uint32_t ab = sbase + slot * GU_STAGE_BYTES;
        const uint32_t bb = ab + GU_A_BYTES;
        #pragma unroll
        for (int i = 0; i < 16; i++) {
            int idx = i * 128 + tid;           // 0..2047
            if (idx < 1024) {                  // A: 128 rows
                int r = idx >> 3, cb = (idx & 7) * 16;
                cp_async16(ab + SWZ(r * 128 + cb), Ag + (size_t)r * pitch + k0b + cb);
            } else {                           // B: 128 virtual rows
                int j = idx - 1024;            // 0..1023
                int r = j >> 3, cb = (j & 7) * 16;
                int blk = r >> 5, within = r & 31;
                int w32 = (blk >> 1) * 32 + within;
                const char* src = (blk & 1) ? Ug : Gg;
                cp_async16(bb + SWZ(r * 128 + cb), src + (size_t)w32 * pitch + k0b + cb);
            }
        }
        cp_commit();
    };

    load_stage(0, 0);
    if (KT > 1) load_stage(1, 1);

    uint32_t arow[4], brow[4];
    #pragma unroll
    for (int mi = 0; mi < 4; mi++)
        arow[mi] = (uint32_t)(wm + mi * 16 + ((g & 1) ? 8 : 0) + li) * 128;
    #pragma unroll
    for (int bi = 0; bi < 4; bi++)
        brow[bi] = (uint32_t)(wn + bi * 16 + ((g >> 1) ? 8 : 0) + li) * 128;
    const uint32_t acol = (g >> 1) ? 16u : 0u;
    const uint32_t bcol = (g & 1) ? 16u : 0u;

    uint32_t af[2][4][4], bf[2][4][4];

    // tile body with compile-time stage slot
    auto tile = [&](auto SLOT_C, int kt) {
        constexpr int SLOT = decltype(SLOT_C)::value;
        const int rem = KT - 1 - kt;
        if (rem >= 1) cp_wait<1>(); else cp_wait<0>();
        __syncthreads();
        if (kt + 2 < KT) load_stage((SLOT + 2) % GU_STAGES, kt + 2);

        const uint32_t ab = sbase + SLOT * GU_STAGE_BYTES;
        const uint32_t bb = ab + GU_A_BYTES;

        #pragma unroll
        for (int mi = 0; mi < 4; mi++)
            ldsm_x4(af[0][mi], ab + SWZ(arow[mi] + acol));
        #pragma unroll
        for (int bi = 0; bi < 4; bi++)
            ldsm_x4(bf[0][bi], bb + SWZ(brow[bi] + bcol));

        #pragma unroll
        for (int ks = 0; ks < 4; ks++) {
            const int cur = ks & 1, nxt = cur ^ 1;
            if (ks < 3) {
                const uint32_t kb = (ks + 1) * 32;
                #pragma unroll
                for (int mi = 0; mi < 4; mi++)
                    ldsm_x4(af[nxt][mi], ab + SWZ(arow[mi] + kb + acol));
                #pragma unroll
                for (int bi = 0; bi < 4; bi++)
                    ldsm_x4(bf[nxt][bi], bb + SWZ(brow[bi] + kb + bcol));
            }
            #pragma unroll
            for (int mi = 0; mi < 4; mi++)
                #pragma unroll
                for (int nj = 0; nj < 8; nj++)
                    mma16816(acc[mi][nj], af[cur][mi], &bf[cur][nj >> 1][(nj & 1) * 2]);
        }
    };

    int kt = 0;
    for (; kt + 3 <= KT; kt += 3) {
        tile(std::integral_constant<int, 0>{}, kt);
        tile(std::integral_constant<int, 1>{}, kt + 1);
        tile(std::integral_constant<int, 2>{}, kt + 2);
    }
    if (kt < KT) { tile(std::integral_constant<int, 0>{}, kt); kt++; }
    if (kt < KT) { tile(std::integral_constant<int, 1>{}, kt); kt++; }

    // epilogue: h = silu(gate*sg/127) * (up*su/127), fp16
    const float inv = 1.0f / 127.0f;
    const int cbase = n0 + (wn >> 1);
    #pragma unroll
    for (int mi = 0; mi < 4; mi++) {
        int r = m0 + wm + mi * 16 + (lane >> 2);
        #pragma unroll
        for (int nj = 0; nj < 4; nj++) {
            int col = cbase + nj * 8 + (lane & 3) * 2;
            float sg0 = sg[col] * inv, sg1 = sg[col + 1] * inv;
            float su0 = su[col] * inv, su1 = su[col + 1] * inv;
            float g00 = acc[mi][nj][0] * sg0, g01 = acc[mi][nj][1] * sg1;
            float g10 = acc[mi][nj][2] * sg0, g11 = acc[mi][nj][3] * sg1;
            float u00 = acc[mi][nj + 4][0] * su0, u01 = acc[mi][nj + 4][1] * su1;
            float u10 = acc[mi][nj + 4][2] * su0, u11 = acc[mi][nj + 4][3] * su1;
            float h00 = u00 * g00 / (1.0f + __expf(-g00));
            float h01 = u01 * g01 / (1.0f + __expf(-g01));
            float h10 = u10 * g10 / (1.0f + __expf(-g10));
            float h11 = u11 * g11 / (1.0f + __expf(-g11));
            *(__half2*)(outp + (size_t)r * N + col)       = __floats2half2_rn(h00, h01);
            *(__half2*)(outp + (size_t)(r + 8) * N + col) = __floats2half2_rn(h10, h11);
        }
    }
}

// ============ down GEMM: 128x128 tile, 128 threads, 2 CTAs/SM ===============
#define DN_STAGES 3
#define DN_A_BYTES (128 * 128)
#define DN_STAGE_BYTES (2 * DN_A_BYTES)            // 32 KB
#define DN_SMEM (DN_STAGES * DN_STAGE_BYTES + 1024)

__global__ __launch_bounds__(128, 2)
void gemm_down(const __half* __restrict__ A, const __half* __restrict__ Bw,
               const float* __restrict__ scale,
               float* __restrict__ outp, int N, int K) {
    extern __shared__ char smem_raw[];
    const uint32_t sbase = (smem_u32(smem_raw) + 1023) & ~1023u;

    const int tid  = threadIdx.x;
    const int lane = tid & 31;
    const int warp = tid >> 5;
    const int wm = (warp >> 1) * 64;          // 0 or 64
    const int wn = (warp & 1) * 64;           // 0 or 64
    const int m0 = blockIdx.x * 128;          // m fastest
    const int n0 = blockIdx.y * 128;
    const int KT = K >> 6;

    const int g  = lane >> 3;
    const int li = lane & 7;

    const size_t pitch = (size_t)K * 2;
    const char* Ag = (const char*)A + (size_t)m0 * pitch;
    const char* Bg = (const char*)Bw + (size_t)n0 * pitch;

    float acc[4][8][4];
    #pragma unroll
    for (int a = 0; a < 4; a++)
        #pragma unroll
        for (int b = 0; b < 8; b++)
            #pragma unroll
            for (int c = 0; c < 4; c++) acc[a][b][c] = 0.f;

    auto load_stage = [&](int slot, int kt) {
        const size_t k0b = (size_t)kt * 128;
        const uint32_t ab = sbase + slot * DN_STAGE_BYTES;
        const uint32_t bb = ab + DN_A_BYTES;
        #pragma unroll
        for (int i = 0; i < 16; i++) {
            int idx = i * 128 + tid;          // 0..2047
            if (idx < 1024) {
                int r = idx >> 3, cb = (idx & 7) * 16;
                cp_async16(ab + SWZ(r * 128 + cb), Ag + (size_t)r * pitch + k0b + cb);
            } else {
                int j = idx - 1024;
                int r = j >> 3, cb = (j & 7) * 16;
                cp_async16(bb + SWZ(r * 128 + cb), Bg + (size_t)r * pitch + k0b + cb);
            }
        }
        cp_commit();
    };

    load_stage(0, 0);
    if (KT > 1) load_stage(1, 1);

    uint32_t arow[4], brow[4];
    #pragma unroll
    for (int mi = 0; mi < 4; mi++)
        arow[mi] = (uint32_t)(wm + mi * 16 + ((g & 1) ? 8 : 0) + li) * 128;
    #pragma unroll
    for (int bi = 0; bi < 4; bi++)
        brow[bi] = (uint32_t)(wn + bi * 16 + ((g >> 1) ? 8 : 0) + li) * 128;
    const uint32_t acol = (g >> 1) ? 16u : 0u;
    const uint32_t bcol = (g & 1) ? 16u : 0u;

    uint32_t af[2][4][4], bf[2][4][4];

    auto tile = [&](auto SLOT_C, int kt) {
        constexpr int SLOT = decltype(SLOT_C)::value;
        const int rem = KT - 1 - kt;
        if (rem >= 1) cp_wait<1>(); else cp_wait<0>();
        __syncthreads();
        if (kt + 2 < KT) load_stage((SLOT + 2) % DN_STAGES, kt + 2);

        const uint32_t ab = sbase + SLOT * DN_STAGE_BYTES;
        const uint32_t bb = ab + DN_A_BYTES;

        #pragma unroll
        for (int mi = 0; mi < 4; mi++)
            ldsm_x4(af[0][mi], ab + SWZ(arow[mi] + acol));
        #pragma unroll
        for (int bi = 0; bi < 4; bi++)
            ldsm_x4(bf[0][bi], bb + SWZ(brow[bi] + bcol));

        #pragma unroll
        for (int ks = 0; ks < 4; ks++) {
            const int cur = ks & 1, nxt = cur ^ 1;
            if (ks < 3) {
                const uint32_t kb = (ks + 1) * 32;
                #pragma unroll
                for (int mi = 0; mi < 4; mi++)
                    ldsm_x4(af[nxt][mi], ab + SWZ(arow[mi] + kb + acol));
                #pragma unroll
                for (int bi = 0; bi < 4; bi++)
                    ldsm_x4(bf[nxt][bi], bb + SWZ(brow[bi] + kb + bcol));
            }
            #pragma unroll
            for (int mi = 0; mi < 4; mi++)
                #pragma unroll
                for (int nj = 0; nj < 8; nj++)
                    mma16816(acc[mi][nj], af[cur][mi], &bf[cur][nj >> 1][(nj & 1) * 2]);
        }
    };

    int kt = 0;
    for (; kt + 3 <= KT; kt += 3) {
        tile(std::integral_constant<int, 0>{}, kt);
        tile(std::integral_constant<int, 1>{}, kt + 1);
        tile(std::integral_constant<int, 2>{}, kt + 2);
    }
    if (kt < KT) { tile(std::integral_constant<int, 0>{}, kt); kt++; }
    if (kt < KT) { tile(std::integral_constant<int, 1>{}, kt); kt++; }

    const float inv = 1.0f / 127.0f;
    #pragma unroll
    for (int mi = 0; mi < 4; mi++) {
        int r = m0 + wm + mi * 16 + (lane >> 2);
        #pragma unroll
        for (int nj = 0; nj < 8; nj++) {
            int col = n0 + wn + nj * 8 + (lane & 3) * 2;
            float s0 = scale[col] * inv;
            float s1 = scale[col + 1] * inv;
            *(float2*)(outp + (size_t)r * N + col) =
                make_float2(acc[mi][nj][0] * s0, acc[mi][nj][1] * s1);
            *(float2*)(outp + (size_t)(r + 8) * N + col) =
                make_float2(acc[mi][nj][2] * s0, acc[mi][nj][3] * s1);
        }
    }
}

// ------------------------------ launcher -----------------------------------
extern "C" void kernel_launch(void* const* d_in, const int* in_sizes, int n_in,
                              void* d_out, int out_size) {
    const float* x  = (const float*)d_in[0];
    const void*  wg = d_in[1];
    const float* sg = (const float*)d_in[2];
    const void*  wu = d_in[3];
    const float* su = (const float*)d_in[4];
    const void*  wd = d_in[5];
    const float* sd = (const float*)d_in[6];

    const int H = in_sizes[6];            // 5120
    const int I = in_sizes[2];            // 12288
    const int M = in_sizes[0] / H;        // 4096

    __half *px16, *pwg, *pwu, *pwd, *ph;
    cudaGetSymbolAddress((void**)&px16, g_x16);
    cudaGetSymbolAddress((void**)&pwg,  g_wg16);
    cudaGetSymbolAddress((void**)&pwu,  g_wu16);
    cudaGetSymbolAddress((void**)&pwd,  g_wd16);
    cudaGetSymbolAddress((void**)&ph,   g_h);

    cudaFuncSetAttribute(gemm_gateup, cudaFuncAttributeMaxDynamicSharedMemorySize, GU_SMEM);
    cudaFuncSetAttribute(gemm_down,   cudaFuncAttributeMaxDynamicSharedMemorySize, DN_SMEM);

    detect_w_kernel<<<1, 32>>>((const int*)wg);

    {
        int n = M * H;
        cvt_f32_f16_kernel<<<(n / 4 + 255) / 256, 256>>>(x, px16, n);
        int nw = I * H;
        dim3 gw((nw / 8 + 255) / 256, 3);
        cvt_w_all_kernel<<<gw, 256>>>(wg, wu, wd, pwg, pwu, pwd, nw);
    }

    // Fused gate+up: h = silu(x@Wg^T*sg/127) * (x@Wu^T*su/127)   [M, I] fp16
    dim3 g1(M / 128, I / 64);    // (32, 192) — 2 CTAs/SM
    gemm_gateup<<<g1, 128, GU_SMEM>>>(px16, pwg, pwu, sg, su, ph, I, H);

    // Down: out = (h @ Wd^T) * sd/127    [M, H] fp32
    dim3 g3(M / 128, H / 128);   // (32, 40) — 2 CTAs/SM
    gemm_down<<<g3, 128, DN_SMEM>>>(ph, pwd, sd, (float*)d_out, H, I);
}

// round 17
// speedup vs baseline: 1.4516x; 1.0617x over previous
#include <cuda_runtime.h>
#include <cuda_fp16.h>
#include <cstdint>
#include <math.h>
#include <type_traits>

// ---------------------------------------------------------------------------
// QuantDeepseekMLP on sm_103a (legacy mma.sync; tcgen05 PTX rejected by the
// harness's compute_103 virtual arch).
// R17: R16's mbarrier-tracked 3-stage cp.async pipeline with the deadlock
// fixed: cp.async.mbarrier.arrive must be the .noinc form (the default form
// increments pending count -> net-zero against count-128 init -> hang).
// Mainloop has NO __syncthreads; warps decouple by up to one stage.
// ---------------------------------------------------------------------------

#define Mdim 4096
#define Hdim 5120
#define Idim 12288

__device__ __half g_x16[(size_t)Mdim * Hdim];
__device__ __half g_wg16[(size_t)Idim * Hdim];
__device__ __half g_wu16[(size_t)Idim * Hdim];
__device__ __half g_wd16[(size_t)Hdim * Idim];
__device__ __half g_h[(size_t)Mdim * Idim];
__device__ int g_wflag;   // 0=int8, 1=int32, 2=float32 weight storage

// ------------------------- dtype detection --------------------------------
__global__ void detect_w_kernel(const int* __restrict__ w) {
    if (threadIdx.x == 0 && blockIdx.x == 0) {
        int all_i32 = 1, all_f32 = 1;
        for (int i = 0; i < 256; i++) {
            int v = w[i];
            if (v < -127 || v > 127) all_i32 = 0;
            float f = __int_as_float(v);
            if (!(isfinite(f) && fabsf(f) <= 127.0f && f == rintf(f)))
                all_f32 = 0;
        }
        g_wflag = all_i32 ? 1 : (all_f32 ? 2 : 0);
    }
}

// ------------------------------ converters --------------------------------
__global__ void cvt_f32_f16_kernel(const float* __restrict__ in,
                                   __half* __restrict__ out, int n) {
    int i = (blockIdx.x * blockDim.x + threadIdx.x) * 4;
    if (i < n) {
        float4 v = *(const float4*)(in + i);
        *(__half2*)(out + i)     = __floats2half2_rn(v.x, v.y);
        *(__half2*)(out + i + 2) = __floats2half2_rn(v.z, v.w);
    }
}

__device__ __forceinline__ void cvt_w8(const void* in, __half* out, int i) {
    const int flag = g_wflag;
    float v[8];
    if (flag == 1) {
        const int4* p = (const int4*)((const int*)in + i);
        int4 a = p[0], b = p[1];
        v[0]=(float)a.x; v[1]=(float)a.y; v[2]=(float)a.z; v[3]=(float)a.w;
        v[4]=(float)b.x; v[5]=(float)b.y; v[6]=(float)b.z; v[7]=(float)b.w;
    } else if (flag == 2) {
        const float4* p = (const float4*)((const float*)in + i);
        float4 a = p[0], b = p[1];
        v[0]=a.x; v[1]=a.y; v[2]=a.z; v[3]=a.w;
        v[4]=b.x; v[5]=b.y; v[6]=b.z; v[7]=b.w;
    } else {
        uint2 raw = *(const uint2*)((const int8_t*)in + i);
        const int8_t* b = (const int8_t*)&raw;
        #pragma unroll
        for (int j = 0; j < 8; j++) v[j] = (float)b[j];
    }
    #pragma unroll
    for (int j = 0; j < 8; j += 2)
        *(__half2*)(out + i + j) = __floats2half2_rn(v[j], v[j + 1]);
}

__global__ void cvt_w_all_kernel(const void* w0, const void* w1, const void* w2,
                                 __half* o0, __half* o1, __half* o2, int n) {
    int i = (blockIdx.x * blockDim.x + threadIdx.x) * 8;
    if (i >= n) return;
    const void* src = (blockIdx.y == 0) ? w0 : (blockIdx.y == 1) ? w1 : w2;
    __half* dst = (blockIdx.y == 0) ? o0 : (blockIdx.y == 1) ? o1 : o2;
    cvt_w8(src, dst, i);
}

// --------------------------- PTX helpers -----------------------------------
__device__ __forceinline__ uint32_t smem_u32(const void* p) {
    return (uint32_t)__cvta_generic_to_shared(p);
}
__device__ __forceinline__ void cp_async16(uint32_t smem, const void* gmem) {
    asm volatile("cp.async.cg.shared.global [%0], [%1], 16;\n" :: "r"(smem), "l"(gmem));
}
__device__ __forceinline__ void mbar_init(uint32_t a, uint32_t cnt) {
    asm volatile("mbarrier.init.shared.b64 [%0], %1;" :: "r"(a), "r"(cnt) : "memory");
}
__device__ __forceinline__ void mbar_arrive(uint32_t a) {
    asm volatile("mbarrier.arrive.shared.b64 _, [%0];" :: "r"(a) : "memory");
}
__device__ __forceinline__ void cp_mbar_arrive(uint32_t a) {
    // .noinc is load-bearing: default form increments pending count first
    // (net zero vs the count-128 init) and the barrier never flips.
    asm volatile("cp.async.mbarrier.arrive.noinc.shared.b64 [%0];" :: "r"(a) : "memory");
}
__device__ __forceinline__ void mbar_wait(uint32_t a, uint32_t parity) {
    asm volatile(
        "{\n\t.reg .pred P;\n"
        "W_%=:\n\t"
        "mbarrier.try_wait.parity.acquire.cta.shared::cta.b64 P, [%0], %1, 0x989680;\n\t"
        "@P bra D_%=;\n\t"
        "bra W_%=;\n"
        "D_%=:\n\t}"
        :: "r"(a), "r"(parity) : "memory");
}
__device__ __forceinline__ void ldsm_x4(uint32_t* r, uint32_t addr) {
    asm volatile("ldmatrix.sync.aligned.m8n8.x4.shared.b16 {%0,%1,%2,%3}, [%4];"
                 : "=r"(r[0]), "=r"(r[1]), "=r"(r[2]), "=r"(r[3]) : "r"(addr));
}
__device__ __forceinline__ void mma16816(float* d, const uint32_t* a,
                                         const uint32_t* b) {
    asm volatile(
        "mma.sync.aligned.m16n8k16.row.col.f32.f16.f16.f32 "
        "{%0,%1,%2,%3}, {%4,%5,%6,%7}, {%8,%9}, {%0,%1,%2,%3};\n"
        : "+f"(d[0]), "+f"(d[1]), "+f"(d[2]), "+f"(d[3])
        : "r"(a[0]), "r"(a[1]), "r"(a[2]), "r"(a[3]), "r"(b[0]), "r"(b[1]));
}

#define SWZ(o) ((o) ^ (((o) >> 3) & 0x70))

// Barrier region at sbase: full[0..2] at +0,+8,+16 ; empty[0..2] at +24,+32,+40
#define MB_FULL(s)  (sbase + 8u * (s))
#define MB_EMPTY(s) (sbase + 24u + 8u * (s))

// =========== fused gate+up GEMM: 128x64 h-tile, 128 thr, 2 CTAs/SM =========
#define GU_STAGES 3
#define GU_A_BYTES (128 * 128)
#define GU_STAGE_BYTES (GU_A_BYTES + 128 * 128)    // 32 KB
#define GU_SMEM (GU_STAGES * GU_STAGE_BYTES + 2048)

__global__ __launch_bounds__(128, 2)
void gemm_gateup(const __half* __restrict__ A, const __half* __restrict__ Bg_w,
                 const __half* __restrict__ Bu_w,
                 const float* __restrict__ sg, const float* __restrict__ su,
                 __half* __restrict__ outp, int N, int K) {
    extern __shared__ char smem_raw[];
    const uint32_t sbase = (smem_u32(smem_raw) + 1023) & ~1023u;
    const uint32_t tbase = sbase + 1024;           // tiles (1024-aligned)

    const int tid  = threadIdx.x;
    const int lane = tid & 31;
    const int warp = tid >> 5;
    const int wm = (warp >> 1) * 64;
    const int wn = (warp & 1) * 64;           // virtual B-row offset
    const int m0 = blockIdx.x * 128;          // m fastest (L2 locality)
    const int n0 = blockIdx.y * 64;           // h column tile (64 wide)
    const int KT = K >> 6;

    const int g  = lane >> 3;
    const int li = lane & 7;

    const size_t pitch = (size_t)K * 2;
    const char* Ag = (const char*)A + (size_t)m0 * pitch;
    const char* Gg = (const char*)Bg_w + (size_t)n0 * pitch;
    const char* Ug = (const char*)Bu_w + (size_t)n0 * pitch;

    float acc[4][8][4];
    #pragma unroll
    for (int a = 0; a < 4; a++)
        #pragma unroll
        for (int b = 0; b < 8; b++)
            #pragma unroll
            for (int c = 0; c < 4; c++) acc[a][b][c] = 0.f;

    auto load_stage = [&](int slot, int kt) {
        const size_t k0b = (size_t)kt * 128;
        const uint32_t ab = tbase + slot * GU_STAGE_BYTES;
        const uint32_t bb = ab + GU_A_BYTES;
        #pragma unroll
        for (int i = 0; i < 16; i++) {
            int idx = i * 128 + tid;           // 0..2047
            if (idx < 1024) {                  // A: 128 rows
                int r = idx >> 3, cb = (idx & 7) * 16;
                cp_async16(ab + SWZ(r * 128 + cb), Ag + (size_t)r * pitch + k0b + cb);
            } else {                           // B: 128 virtual rows
                int j = idx - 1024;            // 0..1023
                int r = j >> 3, cb = (j & 7) * 16;
                int blk = r >> 5, within = r & 31;
                int w32 = (blk >> 1) * 32 + within;
                const char* src = (blk & 1) ? Ug : Gg;
                cp_async16(bb + SWZ(r * 128 + cb), src + (size_t)w32 * pitch + k0b + cb);
            }
        }
    };

    if (tid == 0) {
        #pragma unroll
        for (int s = 0; s < 3; s++) { mbar_init(MB_FULL(s), 128); mbar_init(MB_EMPTY(s), 128); }
    }
    __syncthreads();

    load_stage(0, 0); cp_mbar_arrive(MB_FULL(0));
    if (KT > 1) { load_stage(1, 1); cp_mbar_arrive(MB_FULL(1)); }

    uint32_t arow[4], brow[4];
    #pragma unroll
    for (int mi = 0; mi < 4; mi++)
        arow[mi] = (uint32_t)(wm + mi * 16 + ((g & 1) ? 8 : 0) + li) * 128;
    #pragma unroll
    for (int bi = 0; bi < 4; bi++)
        brow[bi] = (uint32_t)(wn + bi * 16 + ((g >> 1) ? 8 : 0) + li) * 128;
    const uint32_t acol = (g >> 1) ? 16u : 0u;
    const uint32_t bcol = (g & 1) ? 16u : 0u;

    uint32_t af[2][4][4], bf[2][4][4];

    // tile: wait full -> prime LDSM -> produce next -> ks loop (empty arrive @ks2)
    auto tile = [&](auto SLOT_C, int kt, uint32_t fullPar, uint32_t emptyPar,
                    bool skipEmptyWait) {
        constexpr int SLOT = decltype(SLOT_C)::value;
        constexpr int PS = (SLOT + 2) % 3;
        const uint32_t ab = tbase + SLOT * GU_STAGE_BYTES;
        const uint32_t bb = ab + GU_A_BYTES;

        mbar_wait(MB_FULL(SLOT), fullPar);

        #pragma unroll
        for (int mi = 0; mi < 4; mi++)
            ldsm_x4(af[0][mi], ab + SWZ(arow[mi] + acol));
        #pragma unroll
        for (int bi = 0; bi < 4; bi++)
            ldsm_x4(bf[0][bi], bb + SWZ(brow[bi] + bcol));

        if (kt + 2 < KT) {
            if (!skipEmptyWait) mbar_wait(MB_EMPTY(PS), emptyPar);
            load_stage(PS, kt + 2);
            cp_mbar_arrive(MB_FULL(PS));
        }

        #pragma unroll
        for (int ks = 0; ks < 4; ks++) {
            const int cur = ks & 1, nxt = cur ^ 1;
            if (ks < 3) {
                const uint32_t kb = (ks + 1) * 32;
                #pragma unroll
                for (int mi = 0; mi < 4; mi++)
                    ldsm_x4(af[nxt][mi], ab + SWZ(arow[mi] + kb + acol));
                #pragma unroll
                for (int bi = 0; bi < 4; bi++)
                    ldsm_x4(bf[nxt][bi], bb + SWZ(brow[bi] + kb + bcol));
                if (ks == 2) mbar_arrive(MB_EMPTY(SLOT));   // last LDSM of slot done
            }
            #pragma unroll
            for (int mi = 0; mi < 4; mi++)
                #pragma unroll
                for (int nj = 0; nj < 8; nj++)
                    mma16816(acc[mi][nj], af[cur][mi], &bf[cur][nj >> 1][(nj & 1) * 2]);
        }
    };

    int kt = 0;
    uint32_t p = 0;
    for (; kt + 3 <= KT; kt += 3, p ^= 1u) {
        tile(std::integral_constant<int, 0>{}, kt,     p, p ^ 1u, kt == 0);
        tile(std::integral_constant<int, 1>{}, kt + 1, p, p,      false);
        tile(std::integral_constant<int, 2>{}, kt + 2, p, p,      false);
    }
    if (kt < KT) { tile(std::integral_constant<int, 0>{}, kt, p, p ^ 1u, false); kt++; }
    if (kt < KT) { tile(std::integral_constant<int, 1>{}, kt, p, p,      false); kt++; }

    // epilogue: h = silu(gate*sg/127) * (up*su/127), fp16
    const float inv = 1.0f / 127.0f;
    const int cbase = n0 + (wn >> 1);
    #pragma unroll
    for (int mi = 0; mi < 4; mi++) {
        int r = m0 + wm + mi * 16 + (lane >> 2);
        #pragma unroll
        for (int nj = 0; nj < 4; nj++) {
            int col = cbase + nj * 8 + (lane & 3) * 2;
            float sg0 = sg[col] * inv, sg1 = sg[col + 1] * inv;
            float su0 = su[col] * inv, su1 = su[col + 1] * inv;
            float g00 = acc[mi][nj][0] * sg0, g01 = acc[mi][nj][1] * sg1;
            float g10 = acc[mi][nj][2] * sg0, g11 = acc[mi][nj][3] * sg1;
            float u00 = acc[mi][nj + 4][0] * su0, u01 = acc[mi][nj + 4][1] * su1;
            float u10 = acc[mi][nj + 4][2] * su0, u11 = acc[mi][nj + 4][3] * su1;
            float h00 = u00 * g00 / (1.0f + __expf(-g00));
            float h01 = u01 * g01 / (1.0f + __expf(-g01));
            float h10 = u10 * g10 / (1.0f + __expf(-g10));
            float h11 = u11 * g11 / (1.0f + __expf(-g11));
            *(__half2*)(outp + (size_t)r * N + col)       = __floats2half2_rn(h00, h01);
            *(__half2*)(outp + (size_t)(r + 8) * N + col) = __floats2half2_rn(h10, h11);
        }
    }
}

// ============ down GEMM: 128x128 tile, 128 threads, 2 CTAs/SM ===============
#define DN_STAGES 3
#define DN_A_BYTES (128 * 128)
#define DN_STAGE_BYTES (2 * DN_A_BYTES)            // 32 KB
#define DN_SMEM (DN_STAGES * DN_STAGE_BYTES + 2048)

__global__ __launch_bounds__(128, 2)
void gemm_down(const __half* __restrict__ A, const __half* __restrict__ Bw,
               const float* __restrict__ scale,
               float* __restrict__ outp, int N, int K) {
    extern __shared__ char smem_raw[];
    const uint32_t sbase = (smem_u32(smem_raw) + 1023) & ~1023u;
    const uint32_t tbase = sbase + 1024;

    const int tid  = threadIdx.x;
    const int lane = tid & 31;
    const int warp = tid >> 5;
    const int wm = (warp >> 1) * 64;          // 0 or 64
    const int wn = (warp & 1) * 64;           // 0 or 64
    const int m0 = blockIdx.x * 128;          // m fastest
    const int n0 = blockIdx.y * 128;
    const int KT = K >> 6;

    const int g  = lane >> 3;
    const int li = lane & 7;

    const size_t pitch = (size_t)K * 2;
    const char* Ag = (const char*)A + (size_t)m0 * pitch;
    const char* Bg = (const char*)Bw + (size_t)n0 * pitch;

    float acc[4][8][4];
    #pragma unroll
    for (int a = 0; a < 4; a++)
        #pragma unroll
        for (int b = 0; b < 8; b++)
            #pragma unroll
            for (int c = 0; c < 4; c++) acc[a][b][c] = 0.f;

    auto load_stage = [&](int slot, int kt) {
        const size_t k0b = (size_t)kt * 128;
        const uint32_t ab = tbase + slot * DN_STAGE_BYTES;
        const uint32_t bb = ab + DN_A_BYTES;
        #pragma unroll
        for (int i = 0; i < 16; i++) {
            int idx = i * 128 + tid;          // 0..2047
            if (idx < 1024) {
                int r = idx >> 3, cb = (idx & 7) * 16;
                cp_async16(ab + SWZ(r * 128 + cb), Ag + (size_t)r * pitch + k0b + cb);
            } else {
                int j = idx - 1024;
                int r = j >> 3, cb = (j & 7) * 16;
                cp_async16(bb + SWZ(r * 128 + cb), Bg + (size_t)r * pitch + k0b + cb);
            }
        }
    };

    if (tid == 0) {
        #pragma unroll
        for (int s = 0; s < 3; s++) { mbar_init(MB_FULL(s), 128); mbar_init(MB_EMPTY(s), 128); }
    }
    __syncthreads();

    load_stage(0, 0); cp_mbar_arrive(MB_FULL(0));
    if (KT > 1) { load_stage(1, 1); cp_mbar_arrive(MB_FULL(1)); }

    uint32_t arow[4], brow[4];
    #pragma unroll
    for (int mi = 0; mi < 4; mi++)
        arow[mi] = (uint32_t)(wm + mi * 16 + ((g & 1) ? 8 : 0) + li) * 128;
    #pragma unroll
    for (int bi = 0; bi < 4; bi++)
        brow[bi] = (uint32_t)(wn + bi * 16 + ((g >> 1) ? 8 : 0) + li) * 128;
    const uint32_t acol = (g >> 1) ? 16u : 0u;
    const uint32_t bcol = (g & 1) ? 16u : 0u;

    uint32_t af[2][4][4], bf[2][4][4];

    auto tile = [&](auto SLOT_C, int kt, uint32_t fullPar, uint32_t emptyPar,
                    bool skipEmptyWait) {
        constexpr int SLOT = decltype(SLOT_C)::value;
        constexpr int PS = (SLOT + 2) % 3;
        const uint32_t ab = tbase + SLOT * DN_STAGE_BYTES;
        const uint32_t bb = ab + DN_A_BYTES;

        mbar_wait(MB_FULL(SLOT), fullPar);

        #pragma unroll
        for (int mi = 0; mi < 4; mi++)
            ldsm_x4(af[0][mi], ab + SWZ(arow[mi] + acol));
        #pragma unroll
        for (int bi = 0; bi < 4; bi++)
            ldsm_x4(bf[0][bi], bb + SWZ(brow[bi] + bcol));

        if (kt + 2 < KT) {
            if (!skipEmptyWait) mbar_wait(MB_EMPTY(PS), emptyPar);
            load_stage(PS, kt + 2);
            cp_mbar_arrive(MB_FULL(PS));
        }

        #pragma unroll
        for (int ks = 0; ks < 4; ks++) {
            const int cur = ks & 1, nxt = cur ^ 1;
            if (ks < 3) {
                const uint32_t kb = (ks + 1) * 32;
                #pragma unroll
                for (int mi = 0; mi < 4; mi++)
                    ldsm_x4(af[nxt][mi], ab + SWZ(arow[mi] + kb + acol));
                #pragma unroll
                for (int bi = 0; bi < 4; bi++)
                    ldsm_x4(bf[nxt][bi], bb + SWZ(brow[bi] + kb + bcol));
                if (ks == 2) mbar_arrive(MB_EMPTY(SLOT));
            }
            #pragma unroll
            for (int mi = 0; mi < 4; mi++)
                #pragma unroll
                for (int nj = 0; nj < 8; nj++)
                    mma16816(acc[mi][nj], af[cur][mi], &bf[cur][nj >> 1][(nj & 1) * 2]);
        }
    };

    int kt = 0;
    uint32_t p = 0;
    for (; kt + 3 <= KT; kt += 3, p ^= 1u) {
        tile(std::integral_constant<int, 0>{}, kt,     p, p ^ 1u, kt == 0);
        tile(std::integral_constant<int, 1>{}, kt + 1, p, p,      false);
        tile(std::integral_constant<int, 2>{}, kt + 2, p, p,      false);
    }
    if (kt < KT) { tile(std::integral_constant<int, 0>{}, kt, p, p ^ 1u, false); kt++; }
    if (kt < KT) { tile(std::integral_constant<int, 1>{}, kt, p, p,      false); kt++; }

    const float inv = 1.0f / 127.0f;
    #pragma unroll
    for (int mi = 0; mi < 4; mi++) {
        int r = m0 + wm + mi * 16 + (lane >> 2);
        #pragma unroll
        for (int nj = 0; nj < 8; nj++) {
            int col = n0 + wn + nj * 8 + (lane & 3) * 2;
            float s0 = scale[col] * inv;
            float s1 = scale[col + 1] * inv;
            *(float2*)(outp + (size_t)r * N + col) =
                make_float2(acc[mi][nj][0] * s0, acc[mi][nj][1] * s1);
            *(float2*)(outp + (size_t)(r + 8) * N + col) =
                make_float2(acc[mi][nj][2] * s0, acc[mi][nj][3] * s1);
        }
    }
}

// ------------------------------ launcher -----------------------------------
extern "C" void kernel_launch(void* const* d_in, const int* in_sizes, int n_in,
                              void* d_out, int out_size) {
    const float* x  = (const float*)d_in[0];
    const void*  wg = d_in[1];
    const float* sg = (const float*)d_in[2];
    const void*  wu = d_in[3];
    const float* su = (const float*)d_in[4];
    const void*  wd = d_in[5];
    const float* sd = (const float*)d_in[6];

    const int H = in_sizes[6];            // 5120
    const int I = in_sizes[2];            // 12288
    const int M = in_sizes[0] / H;        // 4096

    __half *px16, *pwg, *pwu, *pwd, *ph;
    cudaGetSymbolAddress((void**)&px16, g_x16);
    cudaGetSymbolAddress((void**)&pwg,  g_wg16);
    cudaGetSymbolAddress((void**)&pwu,  g_wu16);
    cudaGetSymbolAddress((void**)&pwd,  g_wd16);
    cudaGetSymbolAddress((void**)&ph,   g_h);

    cudaFuncSetAttribute(gemm_gateup, cudaFuncAttributeMaxDynamicSharedMemorySize, GU_SMEM);
    cudaFuncSetAttribute(gemm_down,   cudaFuncAttributeMaxDynamicSharedMemorySize, DN_SMEM);

    detect_w_kernel<<<1, 32>>>((const int*)wg);

    {
        int n = M * H;
        cvt_f32_f16_kernel<<<(n / 4 + 255) / 256, 256>>>(x, px16, n);
        int nw = I * H;
        dim3 gw((nw / 8 + 255) / 256, 3);
        cvt_w_all_kernel<<<gw, 256>>>(wg, wu, wd, pwg, pwu, pwd, nw);
    }

    // Fused gate+up: h = silu(x@Wg^T*sg/127) * (x@Wu^T*su/127)   [M, I] fp16
    dim3 g1(M / 128, I / 64);    // (32, 192) — 2 CTAs/SM
    gemm_gateup<<<g1, 128, GU_SMEM>>>(px16, pwg, pwu, sg, su, ph, I, H);

    // Down: out = (h @ Wd^T) * sd/127    [M, H] fp32
    dim3 g3(M / 128, H / 128);   // (32, 40) — 2 CTAs/SM
    gemm_down<<<g3, 128, DN_SMEM>>>(ph, pwd, sd, (float*)d_out, H, I);
}